// round 8
// baseline (speedup 1.0000x reference)
#include <cuda_runtime.h>
#include <cuda_bf16.h>

// Scratch (no allocations allowed -> __device__ globals)
__device__ float g_LU[2][128 * 128];     // in-place LU factors of (I - A/2), row-major
__device__ float g_QT[2][128 * 128];     // QT[m][j*128+i] = Q[j][i]  (v_new = v @ Q^T)
__device__ float g_table[4096 * 128];    // pathemb table for every position value

#define LU_PITCH 129

// ---------------------------------------------------------------------------
// Kernel 1: LU factorization (no pivoting; M = I - A/2 has SPD symmetric part).
// 2 blocks, 1024 threads. Warp w owns rows {4w..4w+3}; lane owns cols {lane+32q}.
// X staged into pitch-129 SMEM (coalesced + conflict-free transpose reads).
// One barrier per pivot via double-buffered col/row staging.
// ---------------------------------------------------------------------------
__global__ __launch_bounds__(1024, 1) void lu_kernel(const float* __restrict__ X) {
    extern __shared__ float Xs[];                 // 128 * 129 floats
    __shared__ float colbuf[2][128];
    __shared__ float rowbuf[2][128];

    const int m    = blockIdx.x;
    const float* Xm = X + m * 128 * 128;
    const int t    = threadIdx.x;
    const int w    = t >> 5;
    const int lane = t & 31;

    // coalesced load of X into padded smem
    for (int idx = t; idx < 128 * 128; idx += 1024)
        Xs[(idx >> 7) * LU_PITCH + (idx & 127)] = Xm[idx];
    __syncthreads();

    // init M = I - 0.5*(tril(X) - tril(X)^T) into registers
    float reg[4][4];
#pragma unroll
    for (int s = 0; s < 4; s++) {
        const int r = 4 * w + s;
#pragma unroll
        for (int q = 0; q < 4; q++) {
            const int c = lane + 32 * q;
            float a = (r > c) ? Xs[r * LU_PITCH + c]
                    : ((r < c) ? -Xs[c * LU_PITCH + r] : 0.0f);
            reg[s][q] = ((r == c) ? 1.0f : 0.0f) - 0.5f * a;
        }
    }

    // stage pivot 0 into buffer 0
    if (lane == 0) {
#pragma unroll
        for (int s = 0; s < 4; s++) colbuf[0][4 * w + s] = reg[s][0];
    }
    if (w == 0) {
#pragma unroll
        for (int q = 0; q < 4; q++) rowbuf[0][lane + 32 * q] = reg[0][q];
    }

    for (int k = 0; k < 128; k++) {
        __syncthreads();
        const int p = k & 1;

        if (4 * w + 3 > k) {                     // warp has rows below pivot
            const float pinv = 1.0f / rowbuf[p][k];
            int qmin = (k - lane + 31) >> 5;     // smallest q with lane+32q >= k
#pragma unroll
            for (int s = 0; s < 4; s++) {
                const int r = 4 * w + s;
                if (r > k) {
                    const float l = colbuf[p][r] * pinv;
                    for (int q = qmin; q < 4; q++) {
                        const int c = lane + 32 * q;
                        if (c == k) reg[s][q] = l;                    // store L
                        else        reg[s][q] -= l * rowbuf[p][c];    // Schur update
                    }
                }
            }
        }

        // stage pivot k+1 (post-update values) into the other buffer
        if (k < 127) {
            const int kn = k + 1;
            if (lane == (kn & 31)) {
                const int qq = kn >> 5;
#pragma unroll
                for (int s = 0; s < 4; s++) colbuf[p ^ 1][4 * w + s] = reg[s][qq];
            }
            if (w == (kn >> 2)) {
                const int ss = kn & 3;
#pragma unroll
                for (int q = 0; q < 4; q++) rowbuf[p ^ 1][lane + 32 * q] = reg[ss][q];
            }
        }
    }
    __syncthreads();
    // coalesced store
#pragma unroll
    for (int s = 0; s < 4; s++) {
        const int r = 4 * w + s;
#pragma unroll
        for (int q = 0; q < 4; q++)
            g_LU[m][r * 128 + lane + 32 * q] = reg[s][q];
    }
}

// ---------------------------------------------------------------------------
// Kernel 2: 256 warp-level triangular solves -> Q^T.
// LU staged in SMEM with pitch 129 -> conflict-free COLUMN reads (this was the
// round-7 bottleneck: stride-128 LDG columns = 32 sectors per warp load).
// 32 blocks x 8 warps; block handles 8 RHS of one matrix.
// ---------------------------------------------------------------------------
__global__ __launch_bounds__(256, 1) void solve_kernel(const float* __restrict__ X) {
    extern __shared__ float sm[];
    float* LUs   = sm;                   // 128 * 129
    float* rdiag = sm + 128 * LU_PITCH;  // 128

    const int t    = threadIdx.x;
    const int m    = blockIdx.x >> 4;        // blocks 0..15 -> m=0, 16..31 -> m=1
    const int j    = ((blockIdx.x & 15) << 3) + (t >> 5);
    const int lane = t & 31;
    const float* Xm = X + m * 128 * 128;
    const float* LUg = g_LU[m];

    for (int idx = t; idx < 128 * 128; idx += 256)
        LUs[(idx >> 7) * LU_PITCH + (idx & 127)] = LUg[idx];
    if (t < 128) rdiag[t] = 1.0f / LUg[t * 128 + t];
    __syncthreads();

    // RHS = column j of (I + A/2)
    float y[4];
#pragma unroll
    for (int s = 0; s < 4; s++) {
        const int i = lane + 32 * s;
        float a = (i > j) ? Xm[i * 128 + j] : ((i < j) ? -Xm[j * 128 + i] : 0.0f);
        y[s] = ((i == j) ? 1.0f : 0.0f) + 0.5f * a;
    }
    // forward: L z = r (unit lower). Bank of LUs[i*129+k] = (i+k)%32 -> conflict-free.
    for (int k = 0; k < 127; k++) {
        const float yk = __shfl_sync(0xffffffffu, y[k >> 5], k & 31);
#pragma unroll
        for (int s = 0; s < 4; s++) {
            const int i = lane + 32 * s;
            if (i > k) y[s] -= LUs[i * LU_PITCH + k] * yk;
        }
    }
    // backward: U q = z (reciprocal diagonal precomputed)
    for (int k = 127; k >= 1; k--) {
        float yk = __shfl_sync(0xffffffffu, y[k >> 5], k & 31) * rdiag[k];
        if (lane == (k & 31)) y[k >> 5] = yk;
#pragma unroll
        for (int s = 0; s < 4; s++) {
            const int i = lane + 32 * s;
            if (i < k) y[s] -= LUs[i * LU_PITCH + k] * yk;
        }
    }
    if (lane == 0) y[0] *= rdiag[0];
#pragma unroll
    for (int s = 0; s < 4; s++)
        g_QT[m][j * 128 + lane + 32 * s] = y[s];
}

// ---------------------------------------------------------------------------
// Kernel 3: path-embedding table for every value p in [0, 4096).
// Recursion: pathemb(v + (b+1)*msb(v)) = pathemb(v) @ Q[b]^T.
// Block g owns level-8 root r=128+g and all p>=256 with (p&127)==g.
// ---------------------------------------------------------------------------
#define TBL_SMEM_FLOATS (2 * 16384 + 2 * 2048)
__global__ __launch_bounds__(512, 1) void table_kernel(const float* __restrict__ identity) {
    extern __shared__ float sm[];
    float* Q0s  = sm;
    float* Q1s  = sm + 16384;
    float* bufA = sm + 32768;
    float* bufB = sm + 34816;
    __shared__ int pv[2][16];

    const int t = threadIdx.x;
    const int g = blockIdx.x;      // 0..127
    const int l = t >> 7;          // matvec lane 0..3
    const int j = t & 127;

    {
        const float4* src = (const float4*)g_QT;
        float4* dst = (float4*)sm;
        for (int i = t; i < 8192; i += 512) dst[i] = src[i];
    }
    if (t < 128) bufA[j] = identity[j];
    if (g == 0 && t < 128) {                 // p = 0, 1 -> identity (empty path)
        g_table[0 + j]   = identity[j];
        g_table[128 + j] = identity[j];
    }
    __syncthreads();

    float* cur = bufA;
    float* nxt = bufB;

    // root path: 7 matvecs, writing ancestors at levels 2..8
    for (int d = 0; d < 7; d++) {
        if (t < 128) {
            const int b = (g >> d) & 1;
            const float* Qp = b ? Q1s : Q0s;
            float a0 = 0.f, a1 = 0.f, a2 = 0.f, a3 = 0.f;
            for (int i = 0; i < 128; i += 4) {
                const float4 vv = *(const float4*)(cur + i);
                a0 += vv.x * Qp[(i + 0) * 128 + j];
                a1 += vv.y * Qp[(i + 1) * 128 + j];
                a2 += vv.z * Qp[(i + 2) * 128 + j];
                a3 += vv.w * Qp[(i + 3) * 128 + j];
            }
            const float acc = (a0 + a1) + (a2 + a3);
            nxt[j] = acc;
            const int p = (g & ((2 << d) - 1)) | (2 << d);
            g_table[p * 128 + j] = acc;
        }
        __syncthreads();
        float* tmp = cur; cur = nxt; nxt = tmp;
    }
    if (t == 0) pv[0][0] = 128 + g;
    __syncthreads();

    int cnt = 1, msb = 128, sel = 0;
    for (int lvl = 0; lvl < 4; lvl++) {      // levels 9..12
        const int nch = cnt * 2;
        for (int cb = 0; cb < nch; cb += 4) {
            const int c = cb + l;
            if (c < nch) {
                const int par = c >> 1;
                const int b   = c & 1;
                const int pc  = pv[sel][par] + (b + 1) * msb;
                const float* Qp = b ? Q1s : Q0s;
                const float* vp = cur + par * 128;
                float a0 = 0.f, a1 = 0.f, a2 = 0.f, a3 = 0.f;
                for (int i = 0; i < 128; i += 4) {
                    const float4 vv = *(const float4*)(vp + i);
                    a0 += vv.x * Qp[(i + 0) * 128 + j];
                    a1 += vv.y * Qp[(i + 1) * 128 + j];
                    a2 += vv.z * Qp[(i + 2) * 128 + j];
                    a3 += vv.w * Qp[(i + 3) * 128 + j];
                }
                const float acc = (a0 + a1) + (a2 + a3);
                nxt[c * 128 + j] = acc;
                g_table[pc * 128 + j] = acc;
                if (j == 0) pv[sel ^ 1][c] = pc;
            }
        }
        __syncthreads();
        float* tmp = cur; cur = nxt; nxt = tmp;
        sel ^= 1; cnt = nch; msb <<= 1;
    }
}

// ---------------------------------------------------------------------------
// Kernel 4: final embedding assembly. One warp per token, float4 streaming
// stores (evict-first: don't let the 128MB output thrash the L2-resident table)
// ---------------------------------------------------------------------------
__global__ __launch_bounds__(256) void out_kernel(const int* __restrict__ tt,
                                                  const int* __restrict__ tv,
                                                  const int* __restrict__ np,
                                                  const float* __restrict__ ew,
                                                  float* __restrict__ out) {
    const int warp = threadIdx.x >> 5;
    const int lane = threadIdx.x & 31;
    const int tok  = blockIdx.x * 8 + warp;      // < 131072

    const int ty  = tt[tok];
    const int val = tv[tok];
    const int pos = np[tok];

    const float4 pv4 = *(const float4*)(g_table + pos * 128 + lane * 4);

    float4 cv;
    if (ty == 4) {
        int idx = val < 0 ? 0 : (val > 4095 ? 4095 : val);
        cv = *(const float4*)(g_table + idx * 128 + lane * 4);
    } else if (ty == 1) {
        cv = *(const float4*)(ew + (val + 1) * 128 + lane * 4);
    } else if (ty == 2) {
        cv = *(const float4*)(ew + (val + 5) * 128 + lane * 4);
    } else if (ty == 0) {
        cv = *(const float4*)(ew + lane * 4);
    } else if (ty == 3 && val == -1) {
        cv = *(const float4*)(ew + 10 * 128 + lane * 4);
    } else {
        cv = make_float4(0.f, 0.f, 0.f, 0.f);
    }

    float* o = out + (size_t)tok * 256;
    __stcs((float4*)(o + lane * 4), cv);
    __stcs((float4*)(o + 128 + lane * 4), pv4);
}

// ---------------------------------------------------------------------------
extern "C" void kernel_launch(void* const* d_in, const int* in_sizes, int n_in,
                              void* d_out, int out_size) {
    const int*   tt    = (const int*)d_in[0];   // token_types   [32,4096]
    const int*   tv    = (const int*)d_in[1];   // token_values  [32,4096]
    const int*   np    = (const int*)d_in[2];   // node_positions[32,4096]
    const float* prim  = (const float*)d_in[3]; // primitives    [2,128,128]
    const float* ident = (const float*)d_in[4]; // identity      [1,128]
    const float* ew    = (const float*)d_in[5]; // embed_weight  [11,128]
    float* out = (float*)d_out;

    const int lu_smem    = 128 * LU_PITCH * (int)sizeof(float);
    const int solve_smem = (128 * LU_PITCH + 128) * (int)sizeof(float);
    const int tbl_smem   = TBL_SMEM_FLOATS * (int)sizeof(float);

    cudaFuncSetAttribute(lu_kernel,    cudaFuncAttributeMaxDynamicSharedMemorySize, lu_smem);
    cudaFuncSetAttribute(solve_kernel, cudaFuncAttributeMaxDynamicSharedMemorySize, solve_smem);
    cudaFuncSetAttribute(table_kernel, cudaFuncAttributeMaxDynamicSharedMemorySize, tbl_smem);

    lu_kernel<<<2, 1024, lu_smem>>>(prim);
    solve_kernel<<<32, 256, solve_smem>>>(prim);
    table_kernel<<<128, 512, tbl_smem>>>(ident);
    out_kernel<<<16384, 256>>>(tt, tv, np, ew, out);
}

// round 9
// speedup vs baseline: 2.3470x; 2.3470x over previous
#include <cuda_runtime.h>
#include <cuda_bf16.h>

// Scratch (no allocations allowed -> __device__ globals)
__device__ float g_LU[2][128 * 128];     // LU factors of (I - A/2), row-major
__device__ float g_QT[2][128 * 128];     // QT[m][j*128+i] = Q[j][i]  (v_new = v @ Q^T)
__device__ float g_table[4096 * 128];    // pathemb table for every position value

#define LU_PITCH 129

// ---------------------------------------------------------------------------
// Kernel 1: LU factorization (no pivoting; M = I - A/2 has SPD symmetric part).
// 2 blocks, 1024 threads. Thread (tr=t&31, tc=t>>5) owns rows {tr+32s},
// cols {4tc..4tc+3}. ALL register-array indices are compile-time (no LMEM).
// Single barrier per pivot via double-buffered col/row/pinv staging.
// ---------------------------------------------------------------------------
__global__ __launch_bounds__(1024, 1) void lu_kernel(const float* __restrict__ X) {
    extern __shared__ float Xs[];                 // 128 * 129 floats
    __shared__ float colbuf[2][128];
    __shared__ float rowbuf[2][128];
    __shared__ float pinvbuf[2];

    const int m    = blockIdx.x;
    const float* Xm = X + m * 128 * 128;
    const int t    = threadIdx.x;
    const int tr   = t & 31;        // row lane (varies within warp)
    const int tc   = t >> 5;        // column group (uniform within warp)

    // coalesced load of X into padded smem
    for (int idx = t; idx < 128 * 128; idx += 1024)
        Xs[(idx >> 7) * LU_PITCH + (idx & 127)] = Xm[idx];
    __syncthreads();

    // init M = I - 0.5*(tril(X) - tril(X)^T)  (conflict-free: bank=(r+c)%32)
    float reg[4][4];
#pragma unroll
    for (int s = 0; s < 4; s++) {
        const int r = tr + 32 * s;
#pragma unroll
        for (int q = 0; q < 4; q++) {
            const int c = 4 * tc + q;
            float a = (r > c) ? Xs[r * LU_PITCH + c]
                    : ((r < c) ? -Xs[c * LU_PITCH + r] : 0.0f);
            reg[s][q] = ((r == c) ? 1.0f : 0.0f) - 0.5f * a;
        }
    }

    // stage pivot 0 into buffer 0
    if (tc == 0) {
#pragma unroll
        for (int s = 0; s < 4; s++) colbuf[0][tr + 32 * s] = reg[s][0];
    }
    if (tr == 0) {
#pragma unroll
        for (int q = 0; q < 4; q++) rowbuf[0][4 * tc + q] = reg[0][q];
        if (tc == 0) pinvbuf[0] = 1.0f / reg[0][0];
    }

    for (int k = 0; k < 128; k++) {
        __syncthreads();
        const int p = k & 1;
        const float pinv = pinvbuf[p];

        float l[4];
#pragma unroll
        for (int s = 0; s < 4; s++) l[s] = colbuf[p][tr + 32 * s] * pinv;

#pragma unroll
        for (int s = 0; s < 4; s++) {
            const int r = tr + 32 * s;
            const bool act = (r > k);
#pragma unroll
            for (int q = 0; q < 4; q++) {
                const int c = 4 * tc + q;
                if (act) {
                    if (c > k)       reg[s][q] -= l[s] * rowbuf[p][c];  // Schur
                    else if (c == k) reg[s][q]  = l[s];                 // store L
                }
            }
        }

        // stage pivot k+1 (post-update values) into the other buffer.
        // Runtime column/row selection done via unrolled select chains
        // (predicated moves) -- NEVER dynamic register-array indexing.
        if (k < 127) {
            const int kn = k + 1;
            if (tc == (kn >> 2)) {                 // this warp owns column kn
                const int qn = kn & 3;
#pragma unroll
                for (int s = 0; s < 4; s++) {
                    float v = reg[s][0];
#pragma unroll
                    for (int qq = 1; qq < 4; qq++)
                        if (qq == qn) v = reg[s][qq];
                    colbuf[p ^ 1][tr + 32 * s] = v;
                }
            }
            if (tr == (kn & 31)) {                 // this lane owns row kn
                const int sn = kn >> 5;
                float vr0 = reg[0][0], vr1 = reg[0][1], vr2 = reg[0][2], vr3 = reg[0][3];
#pragma unroll
                for (int ss = 1; ss < 4; ss++) {
                    if (ss == sn) { vr0 = reg[ss][0]; vr1 = reg[ss][1];
                                    vr2 = reg[ss][2]; vr3 = reg[ss][3]; }
                }
                rowbuf[p ^ 1][4 * tc + 0] = vr0;
                rowbuf[p ^ 1][4 * tc + 1] = vr1;
                rowbuf[p ^ 1][4 * tc + 2] = vr2;
                rowbuf[p ^ 1][4 * tc + 3] = vr3;
                if (tc == (kn >> 2)) {             // this thread owns (kn, kn)
                    const int qn = kn & 3;
                    float v = vr0;
                    if (qn == 1) v = vr1;
                    if (qn == 2) v = vr2;
                    if (qn == 3) v = vr3;
                    pinvbuf[p ^ 1] = 1.0f / v;
                }
            }
        }
    }
    __syncthreads();

    // store via smem transpose -> coalesced g_LU write
#pragma unroll
    for (int s = 0; s < 4; s++) {
        const int r = tr + 32 * s;
#pragma unroll
        for (int q = 0; q < 4; q++)
            Xs[r * LU_PITCH + 4 * tc + q] = reg[s][q];
    }
    __syncthreads();
    for (int idx = t; idx < 128 * 128; idx += 1024)
        g_LU[m][idx] = Xs[(idx >> 7) * LU_PITCH + (idx & 127)];
}

// ---------------------------------------------------------------------------
// Kernel 2: 256 warp-level triangular solves -> Q^T.
// LU staged in SMEM with pitch 129 (conflict-free column reads). The 128-step
// recurrences are split into 4 explicit segments so y0..y3 stay in registers
// (no dynamic indexing -> no local memory). 32 blocks x 8 warps.
// ---------------------------------------------------------------------------
__global__ __launch_bounds__(256, 1) void solve_kernel(const float* __restrict__ X) {
    extern __shared__ float sm[];
    float* LUs   = sm;                   // 128 * 129
    float* rdiag = sm + 128 * LU_PITCH;  // 128

    const int t    = threadIdx.x;
    const int m    = blockIdx.x >> 4;
    const int j    = ((blockIdx.x & 15) << 3) + (t >> 5);
    const int lane = t & 31;
    const float* Xm  = X + m * 128 * 128;
    const float* LUg = g_LU[m];

    for (int idx = t; idx < 128 * 128; idx += 256)
        LUs[(idx >> 7) * LU_PITCH + (idx & 127)] = LUg[idx];
    if (t < 128) rdiag[t] = 1.0f / LUg[t * 128 + t];
    __syncthreads();

    // RHS = column j of (I + A/2)
    float y0, y1, y2, y3;
    {
        const int i0 = lane, i1 = lane + 32, i2 = lane + 64, i3 = lane + 96;
        float a0 = (i0 > j) ? Xm[i0 * 128 + j] : ((i0 < j) ? -Xm[j * 128 + i0] : 0.0f);
        float a1 = (i1 > j) ? Xm[i1 * 128 + j] : ((i1 < j) ? -Xm[j * 128 + i1] : 0.0f);
        float a2 = (i2 > j) ? Xm[i2 * 128 + j] : ((i2 < j) ? -Xm[j * 128 + i2] : 0.0f);
        float a3 = (i3 > j) ? Xm[i3 * 128 + j] : 0.0f;  // i3 >= 96 > j possible only if j<96... keep general:
        if (i3 < j) a3 = -Xm[j * 128 + i3];
        y0 = ((i0 == j) ? 1.0f : 0.0f) + 0.5f * a0;
        y1 = ((i1 == j) ? 1.0f : 0.0f) + 0.5f * a1;
        y2 = ((i2 == j) ? 1.0f : 0.0f) + 0.5f * a2;
        y3 = ((i3 == j) ? 1.0f : 0.0f) + 0.5f * a3;
    }

    const unsigned FULL = 0xffffffffu;

    // ---- forward: L z = r (unit lower) ----
#pragma unroll 4
    for (int kk = 0; kk < 32; kk++) {              // k = kk
        const float yk = __shfl_sync(FULL, y0, kk);
        const float* col = LUs + kk;
        if (lane > kk) y0 -= col[lane * LU_PITCH] * yk;
        y1 -= col[(lane + 32) * LU_PITCH] * yk;
        y2 -= col[(lane + 64) * LU_PITCH] * yk;
        y3 -= col[(lane + 96) * LU_PITCH] * yk;
    }
#pragma unroll 4
    for (int kk = 0; kk < 32; kk++) {              // k = 32 + kk
        const float yk = __shfl_sync(FULL, y1, kk);
        const float* col = LUs + 32 + kk;
        if (lane > kk) y1 -= col[(lane + 32) * LU_PITCH] * yk;
        y2 -= col[(lane + 64) * LU_PITCH] * yk;
        y3 -= col[(lane + 96) * LU_PITCH] * yk;
    }
#pragma unroll 4
    for (int kk = 0; kk < 32; kk++) {              // k = 64 + kk
        const float yk = __shfl_sync(FULL, y2, kk);
        const float* col = LUs + 64 + kk;
        if (lane > kk) y2 -= col[(lane + 64) * LU_PITCH] * yk;
        y3 -= col[(lane + 96) * LU_PITCH] * yk;
    }
#pragma unroll 4
    for (int kk = 0; kk < 31; kk++) {              // k = 96 + kk (last row needs no fwd)
        const float yk = __shfl_sync(FULL, y3, kk);
        if (lane > kk) y3 -= LUs[(lane + 96) * LU_PITCH + 96 + kk] * yk;
    }

    // ---- backward: U q = z ----
#pragma unroll 4
    for (int kk = 31; kk >= 0; kk--) {             // k = 96 + kk
        const int k = 96 + kk;
        const float yk = __shfl_sync(FULL, y3, kk) * rdiag[k];
        if (lane == kk) y3 = yk;
        else if (lane < kk) y3 -= LUs[(lane + 96) * LU_PITCH + k] * yk;
        y0 -= LUs[lane * LU_PITCH + k] * yk;
        y1 -= LUs[(lane + 32) * LU_PITCH + k] * yk;
        y2 -= LUs[(lane + 64) * LU_PITCH + k] * yk;
    }
#pragma unroll 4
    for (int kk = 31; kk >= 0; kk--) {             // k = 64 + kk
        const int k = 64 + kk;
        const float yk = __shfl_sync(FULL, y2, kk) * rdiag[k];
        if (lane == kk) y2 = yk;
        else if (lane < kk) y2 -= LUs[(lane + 64) * LU_PITCH + k] * yk;
        y0 -= LUs[lane * LU_PITCH + k] * yk;
        y1 -= LUs[(lane + 32) * LU_PITCH + k] * yk;
    }
#pragma unroll 4
    for (int kk = 31; kk >= 0; kk--) {             // k = 32 + kk
        const int k = 32 + kk;
        const float yk = __shfl_sync(FULL, y1, kk) * rdiag[k];
        if (lane == kk) y1 = yk;
        else if (lane < kk) y1 -= LUs[(lane + 32) * LU_PITCH + k] * yk;
        y0 -= LUs[lane * LU_PITCH + k] * yk;
    }
#pragma unroll 4
    for (int kk = 31; kk >= 0; kk--) {             // k = kk
        const float yk = __shfl_sync(FULL, y0, kk) * rdiag[kk];
        if (lane == kk) y0 = yk;
        else if (lane < kk) y0 -= LUs[lane * LU_PITCH + kk] * yk;
    }

    // coalesced QT row write: QT[m][j][i] = q_i
    float* dst = g_QT[m] + j * 128 + lane;
    dst[0]  = y0;
    dst[32] = y1;
    dst[64] = y2;
    dst[96] = y3;
}

// ---------------------------------------------------------------------------
// Kernel 3: path-embedding table for every value p in [0, 4096).
// Recursion: pathemb(v + (b+1)*msb(v)) = pathemb(v) @ Q[b]^T.
// Block g owns level-8 root r=128+g and all p>=256 with (p&127)==g.
// ---------------------------------------------------------------------------
#define TBL_SMEM_FLOATS (2 * 16384 + 2 * 2048)
__global__ __launch_bounds__(512, 1) void table_kernel(const float* __restrict__ identity) {
    extern __shared__ float sm[];
    float* Q0s  = sm;
    float* Q1s  = sm + 16384;
    float* bufA = sm + 32768;
    float* bufB = sm + 34816;
    __shared__ int pv[2][16];

    const int t = threadIdx.x;
    const int g = blockIdx.x;      // 0..127
    const int l = t >> 7;          // matvec lane 0..3
    const int j = t & 127;

    {
        const float4* src = (const float4*)g_QT;
        float4* dst = (float4*)sm;
        for (int i = t; i < 8192; i += 512) dst[i] = src[i];
    }
    if (t < 128) bufA[j] = identity[j];
    if (g == 0 && t < 128) {                 // p = 0, 1 -> identity (empty path)
        g_table[0 + j]   = identity[j];
        g_table[128 + j] = identity[j];
    }
    __syncthreads();

    float* cur = bufA;
    float* nxt = bufB;

    // root path: 7 matvecs, writing ancestors at levels 2..8
    for (int d = 0; d < 7; d++) {
        if (t < 128) {
            const int b = (g >> d) & 1;
            const float* Qp = b ? Q1s : Q0s;
            float a0 = 0.f, a1 = 0.f, a2 = 0.f, a3 = 0.f;
            for (int i = 0; i < 128; i += 4) {
                const float4 vv = *(const float4*)(cur + i);
                a0 += vv.x * Qp[(i + 0) * 128 + j];
                a1 += vv.y * Qp[(i + 1) * 128 + j];
                a2 += vv.z * Qp[(i + 2) * 128 + j];
                a3 += vv.w * Qp[(i + 3) * 128 + j];
            }
            const float acc = (a0 + a1) + (a2 + a3);
            nxt[j] = acc;
            const int p = (g & ((2 << d) - 1)) | (2 << d);
            g_table[p * 128 + j] = acc;
        }
        __syncthreads();
        float* tmp = cur; cur = nxt; nxt = tmp;
    }
    if (t == 0) pv[0][0] = 128 + g;
    __syncthreads();

    int cnt = 1, msb = 128, sel = 0;
    for (int lvl = 0; lvl < 4; lvl++) {      // levels 9..12
        const int nch = cnt * 2;
        for (int cb = 0; cb < nch; cb += 4) {
            const int c = cb + l;
            if (c < nch) {
                const int par = c >> 1;
                const int b   = c & 1;
                const int pc  = pv[sel][par] + (b + 1) * msb;
                const float* Qp = b ? Q1s : Q0s;
                const float* vp = cur + par * 128;
                float a0 = 0.f, a1 = 0.f, a2 = 0.f, a3 = 0.f;
                for (int i = 0; i < 128; i += 4) {
                    const float4 vv = *(const float4*)(vp + i);
                    a0 += vv.x * Qp[(i + 0) * 128 + j];
                    a1 += vv.y * Qp[(i + 1) * 128 + j];
                    a2 += vv.z * Qp[(i + 2) * 128 + j];
                    a3 += vv.w * Qp[(i + 3) * 128 + j];
                }
                const float acc = (a0 + a1) + (a2 + a3);
                nxt[c * 128 + j] = acc;
                g_table[pc * 128 + j] = acc;
                if (j == 0) pv[sel ^ 1][c] = pc;
            }
        }
        __syncthreads();
        float* tmp = cur; cur = nxt; nxt = tmp;
        sel ^= 1; cnt = nch; msb <<= 1;
    }
}

// ---------------------------------------------------------------------------
// Kernel 4: final embedding assembly. One warp per token, float4 streaming
// stores. 128 MB write -> HBM-bound.
// ---------------------------------------------------------------------------
__global__ __launch_bounds__(256) void out_kernel(const int* __restrict__ tt,
                                                  const int* __restrict__ tv,
                                                  const int* __restrict__ np,
                                                  const float* __restrict__ ew,
                                                  float* __restrict__ out) {
    const int warp = threadIdx.x >> 5;
    const int lane = threadIdx.x & 31;
    const int tok  = blockIdx.x * 8 + warp;      // < 131072

    const int ty  = tt[tok];
    const int val = tv[tok];
    const int pos = np[tok];

    const float4 pv4 = *(const float4*)(g_table + pos * 128 + lane * 4);

    float4 cv;
    if (ty == 4) {
        int idx = val < 0 ? 0 : (val > 4095 ? 4095 : val);
        cv = *(const float4*)(g_table + idx * 128 + lane * 4);
    } else if (ty == 1) {
        cv = *(const float4*)(ew + (val + 1) * 128 + lane * 4);
    } else if (ty == 2) {
        cv = *(const float4*)(ew + (val + 5) * 128 + lane * 4);
    } else if (ty == 0) {
        cv = *(const float4*)(ew + lane * 4);
    } else if (ty == 3 && val == -1) {
        cv = *(const float4*)(ew + 10 * 128 + lane * 4);
    } else {
        cv = make_float4(0.f, 0.f, 0.f, 0.f);
    }

    float* o = out + (size_t)tok * 256;
    __stcs((float4*)(o + lane * 4), cv);
    __stcs((float4*)(o + 128 + lane * 4), pv4);
}

// ---------------------------------------------------------------------------
extern "C" void kernel_launch(void* const* d_in, const int* in_sizes, int n_in,
                              void* d_out, int out_size) {
    const int*   tt    = (const int*)d_in[0];   // token_types   [32,4096]
    const int*   tv    = (const int*)d_in[1];   // token_values  [32,4096]
    const int*   np    = (const int*)d_in[2];   // node_positions[32,4096]
    const float* prim  = (const float*)d_in[3]; // primitives    [2,128,128]
    const float* ident = (const float*)d_in[4]; // identity      [1,128]
    const float* ew    = (const float*)d_in[5]; // embed_weight  [11,128]
    float* out = (float*)d_out;

    const int lu_smem    = 128 * LU_PITCH * (int)sizeof(float);
    const int solve_smem = (128 * LU_PITCH + 128) * (int)sizeof(float);
    const int tbl_smem   = TBL_SMEM_FLOATS * (int)sizeof(float);

    cudaFuncSetAttribute(lu_kernel,    cudaFuncAttributeMaxDynamicSharedMemorySize, lu_smem);
    cudaFuncSetAttribute(solve_kernel, cudaFuncAttributeMaxDynamicSharedMemorySize, solve_smem);
    cudaFuncSetAttribute(table_kernel, cudaFuncAttributeMaxDynamicSharedMemorySize, tbl_smem);

    lu_kernel<<<2, 1024, lu_smem>>>(prim);
    solve_kernel<<<32, 256, solve_smem>>>(prim);
    table_kernel<<<128, 512, tbl_smem>>>(ident);
    out_kernel<<<16384, 256>>>(tt, tv, np, ew, out);
}

// round 10
// speedup vs baseline: 2.4526x; 1.0450x over previous
#include <cuda_runtime.h>
#include <cuda_bf16.h>

// Scratch (no allocations allowed -> __device__ globals)
__device__ float g_LU[2][128 * 128];     // LU factors of (I - A/2), row-major
__device__ float g_QT[2][128 * 128];     // QT[m][j*128+i] = Q[j][i]  (v_new = v @ Q^T)
__device__ float g_table[4096 * 128];    // pathemb table for every position value

#define LU_PITCH 129

// ---------------------------------------------------------------------------
// Kernel 1: LU factorization (no pivoting; M = I - A/2 has SPD symmetric part).
// 2 blocks x 512 threads (16 warps). Warp w owns COLUMNS 8w..8w+7 (so a warp
// whose columns are all left of the pivot is uniformly dead and skips the
// step body). Lane tr owns rows {tr+32s}. All register indices compile-time.
// Single barrier per pivot, double-buffered col/row/pinv staging.
// ---------------------------------------------------------------------------
__global__ __launch_bounds__(512, 1) void lu_kernel(const float* __restrict__ X) {
    extern __shared__ float Xs[];                 // 128 * 129 floats
    __shared__ float colbuf[2][128];
    __shared__ float rowbuf[2][128];
    __shared__ float pinvbuf[2];

    const int m    = blockIdx.x;
    const float* Xm = X + m * 128 * 128;
    const int t    = threadIdx.x;
    const int tr   = t & 31;        // row lane
    const int w    = t >> 5;        // warp id = column group (warp-uniform)

    for (int idx = t; idx < 128 * 128; idx += 512)
        Xs[(idx >> 7) * LU_PITCH + (idx & 127)] = Xm[idx];
    __syncthreads();

    // init M = I - 0.5*(tril(X) - tril(X)^T)  (pitch-129: conflict-free)
    float reg[4][8];
#pragma unroll
    for (int s = 0; s < 4; s++) {
        const int r = tr + 32 * s;
#pragma unroll
        for (int q = 0; q < 8; q++) {
            const int c = 8 * w + q;
            float a = (r > c) ? Xs[r * LU_PITCH + c]
                    : ((r < c) ? -Xs[c * LU_PITCH + r] : 0.0f);
            reg[s][q] = ((r == c) ? 1.0f : 0.0f) - 0.5f * a;
        }
    }

    // stage pivot 0 into buffer 0
    if (w == 0) {
#pragma unroll
        for (int s = 0; s < 4; s++) colbuf[0][tr + 32 * s] = reg[s][0];
    }
    if (tr == 0) {
#pragma unroll
        for (int q = 0; q < 8; q++) rowbuf[0][8 * w + q] = reg[0][q];
        if (w == 0) pinvbuf[0] = 1.0f / reg[0][0];
    }

    for (int k = 0; k < 128; k++) {
        __syncthreads();
        const int p = k & 1;

        if (8 * w + 7 >= k) {                     // warp-uniform dead skip
            const float pinv = pinvbuf[p];
            float l[4];
#pragma unroll
            for (int s = 0; s < 4; s++) l[s] = colbuf[p][tr + 32 * s] * pinv;
            float rb[8];
#pragma unroll
            for (int q = 0; q < 8; q++) rb[q] = rowbuf[p][8 * w + q];

#pragma unroll
            for (int s = 0; s < 4; s++) {
                const int r = tr + 32 * s;
                const bool act = (r > k);
#pragma unroll
                for (int q = 0; q < 8; q++) {
                    const int c = 8 * w + q;
                    if (act) {
                        if (c > k)       reg[s][q] -= l[s] * rb[q];   // Schur
                        else if (c == k) reg[s][q]  = l[s];           // store L
                    }
                }
            }

            // stage pivot k+1 into the other buffer (compile-time select chains)
            if (k < 127) {
                const int kn = k + 1;
                if (w == (kn >> 3)) {              // column kn owner warp
                    const int qn = kn & 7;
#pragma unroll
                    for (int s = 0; s < 4; s++) {
                        float v = reg[s][0];
#pragma unroll
                        for (int qq = 1; qq < 8; qq++)
                            if (qq == qn) v = reg[s][qq];
                        colbuf[p ^ 1][tr + 32 * s] = v;
                    }
                }
                if (tr == (kn & 31)) {             // row kn lane (active warps)
                    const int sn = kn >> 5;
                    float vr[8];
#pragma unroll
                    for (int q = 0; q < 8; q++) {
                        float v = reg[0][q];
#pragma unroll
                        for (int ss = 1; ss < 4; ss++)
                            if (ss == sn) v = reg[ss][q];
                        vr[q] = v;
                        rowbuf[p ^ 1][8 * w + q] = v;
                    }
                    if (w == (kn >> 3)) {          // (kn, kn) owner thread
                        const int qn = kn & 7;
                        float v = vr[0];
#pragma unroll
                        for (int qq = 1; qq < 8; qq++)
                            if (qq == qn) v = vr[qq];
                        pinvbuf[p ^ 1] = 1.0f / v;
                    }
                }
            }
        }
    }
    __syncthreads();

    // store via smem -> coalesced g_LU write
#pragma unroll
    for (int s = 0; s < 4; s++) {
        const int r = tr + 32 * s;
#pragma unroll
        for (int q = 0; q < 8; q++)
            Xs[r * LU_PITCH + 8 * w + q] = reg[s][q];
    }
    __syncthreads();
    for (int idx = t; idx < 128 * 128; idx += 512)
        g_LU[m][idx] = Xs[(idx >> 7) * LU_PITCH + (idx & 127)];
}

// ---------------------------------------------------------------------------
// Kernel 2: 256 warp-level triangular solves -> Q^T.
// LU staged in SMEM pitch-129 (conflict-free column reads); 128-step
// recurrences split into 4 segments so y0..y3 stay in registers.
// ---------------------------------------------------------------------------
__global__ __launch_bounds__(256, 1) void solve_kernel(const float* __restrict__ X) {
    extern __shared__ float sm[];
    float* LUs   = sm;                   // 128 * 129
    float* rdiag = sm + 128 * LU_PITCH;  // 128

    const int t    = threadIdx.x;
    const int m    = blockIdx.x >> 4;
    const int j    = ((blockIdx.x & 15) << 3) + (t >> 5);
    const int lane = t & 31;
    const float* Xm  = X + m * 128 * 128;
    const float* LUg = g_LU[m];

    for (int idx = t; idx < 128 * 128; idx += 256)
        LUs[(idx >> 7) * LU_PITCH + (idx & 127)] = LUg[idx];
    if (t < 128) rdiag[t] = 1.0f / LUg[t * 128 + t];
    __syncthreads();

    // RHS = column j of (I + A/2)
    float y0, y1, y2, y3;
    {
        const int i0 = lane, i1 = lane + 32, i2 = lane + 64, i3 = lane + 96;
        float a0 = (i0 > j) ? Xm[i0 * 128 + j] : ((i0 < j) ? -Xm[j * 128 + i0] : 0.0f);
        float a1 = (i1 > j) ? Xm[i1 * 128 + j] : ((i1 < j) ? -Xm[j * 128 + i1] : 0.0f);
        float a2 = (i2 > j) ? Xm[i2 * 128 + j] : ((i2 < j) ? -Xm[j * 128 + i2] : 0.0f);
        float a3 = (i3 > j) ? Xm[i3 * 128 + j] : ((i3 < j) ? -Xm[j * 128 + i3] : 0.0f);
        y0 = ((i0 == j) ? 1.0f : 0.0f) + 0.5f * a0;
        y1 = ((i1 == j) ? 1.0f : 0.0f) + 0.5f * a1;
        y2 = ((i2 == j) ? 1.0f : 0.0f) + 0.5f * a2;
        y3 = ((i3 == j) ? 1.0f : 0.0f) + 0.5f * a3;
    }

    const unsigned FULL = 0xffffffffu;

    // forward: L z = r (unit lower)
#pragma unroll 4
    for (int kk = 0; kk < 32; kk++) {
        const float yk = __shfl_sync(FULL, y0, kk);
        const float* col = LUs + kk;
        if (lane > kk) y0 -= col[lane * LU_PITCH] * yk;
        y1 -= col[(lane + 32) * LU_PITCH] * yk;
        y2 -= col[(lane + 64) * LU_PITCH] * yk;
        y3 -= col[(lane + 96) * LU_PITCH] * yk;
    }
#pragma unroll 4
    for (int kk = 0; kk < 32; kk++) {
        const float yk = __shfl_sync(FULL, y1, kk);
        const float* col = LUs + 32 + kk;
        if (lane > kk) y1 -= col[(lane + 32) * LU_PITCH] * yk;
        y2 -= col[(lane + 64) * LU_PITCH] * yk;
        y3 -= col[(lane + 96) * LU_PITCH] * yk;
    }
#pragma unroll 4
    for (int kk = 0; kk < 32; kk++) {
        const float yk = __shfl_sync(FULL, y2, kk);
        const float* col = LUs + 64 + kk;
        if (lane > kk) y2 -= col[(lane + 64) * LU_PITCH] * yk;
        y3 -= col[(lane + 96) * LU_PITCH] * yk;
    }
#pragma unroll 4
    for (int kk = 0; kk < 31; kk++) {
        const float yk = __shfl_sync(FULL, y3, kk);
        if (lane > kk) y3 -= LUs[(lane + 96) * LU_PITCH + 96 + kk] * yk;
    }

    // backward: U q = z
#pragma unroll 4
    for (int kk = 31; kk >= 0; kk--) {
        const int k = 96 + kk;
        const float yk = __shfl_sync(FULL, y3, kk) * rdiag[k];
        if (lane == kk) y3 = yk;
        else if (lane < kk) y3 -= LUs[(lane + 96) * LU_PITCH + k] * yk;
        y0 -= LUs[lane * LU_PITCH + k] * yk;
        y1 -= LUs[(lane + 32) * LU_PITCH + k] * yk;
        y2 -= LUs[(lane + 64) * LU_PITCH + k] * yk;
    }
#pragma unroll 4
    for (int kk = 31; kk >= 0; kk--) {
        const int k = 64 + kk;
        const float yk = __shfl_sync(FULL, y2, kk) * rdiag[k];
        if (lane == kk) y2 = yk;
        else if (lane < kk) y2 -= LUs[(lane + 64) * LU_PITCH + k] * yk;
        y0 -= LUs[lane * LU_PITCH + k] * yk;
        y1 -= LUs[(lane + 32) * LU_PITCH + k] * yk;
    }
#pragma unroll 4
    for (int kk = 31; kk >= 0; kk--) {
        const int k = 32 + kk;
        const float yk = __shfl_sync(FULL, y1, kk) * rdiag[k];
        if (lane == kk) y1 = yk;
        else if (lane < kk) y1 -= LUs[(lane + 32) * LU_PITCH + k] * yk;
        y0 -= LUs[lane * LU_PITCH + k] * yk;
    }
#pragma unroll 4
    for (int kk = 31; kk >= 0; kk--) {
        const float yk = __shfl_sync(FULL, y0, kk) * rdiag[kk];
        if (lane == kk) y0 = yk;
        else if (lane < kk) y0 -= LUs[lane * LU_PITCH + kk] * yk;
    }

    float* dst = g_QT[m] + j * 128 + lane;
    dst[0]  = y0;
    dst[32] = y1;
    dst[64] = y2;
    dst[96] = y3;
}

// ---------------------------------------------------------------------------
// Kernel 3: path-embedding table for every value p in [0, 4096).
// Recursion: pathemb(v + (b+1)*msb(v)) = pathemb(v) @ Q[b]^T.
// Block g owns level-8 root r=128+g and all p>=256 with (p&127)==g.
// ---------------------------------------------------------------------------
#define TBL_SMEM_FLOATS (2 * 16384 + 2 * 2048)
__global__ __launch_bounds__(512, 1) void table_kernel(const float* __restrict__ identity) {
    extern __shared__ float sm[];
    float* Q0s  = sm;
    float* Q1s  = sm + 16384;
    float* bufA = sm + 32768;
    float* bufB = sm + 34816;
    __shared__ int pv[2][16];

    const int t = threadIdx.x;
    const int g = blockIdx.x;      // 0..127
    const int l = t >> 7;          // matvec lane 0..3
    const int j = t & 127;

    {
        const float4* src = (const float4*)g_QT;
        float4* dst = (float4*)sm;
        for (int i = t; i < 8192; i += 512) dst[i] = src[i];
    }
    if (t < 128) bufA[j] = identity[j];
    if (g == 0 && t < 128) {                 // p = 0, 1 -> identity (empty path)
        g_table[0 + j]   = identity[j];
        g_table[128 + j] = identity[j];
    }
    __syncthreads();

    float* cur = bufA;
    float* nxt = bufB;

    for (int d = 0; d < 7; d++) {            // root path: levels 2..8
        if (t < 128) {
            const int b = (g >> d) & 1;
            const float* Qp = b ? Q1s : Q0s;
            float a0 = 0.f, a1 = 0.f, a2 = 0.f, a3 = 0.f;
            for (int i = 0; i < 128; i += 4) {
                const float4 vv = *(const float4*)(cur + i);
                a0 += vv.x * Qp[(i + 0) * 128 + j];
                a1 += vv.y * Qp[(i + 1) * 128 + j];
                a2 += vv.z * Qp[(i + 2) * 128 + j];
                a3 += vv.w * Qp[(i + 3) * 128 + j];
            }
            const float acc = (a0 + a1) + (a2 + a3);
            nxt[j] = acc;
            const int p = (g & ((2 << d) - 1)) | (2 << d);
            g_table[p * 128 + j] = acc;
        }
        __syncthreads();
        float* tmp = cur; cur = nxt; nxt = tmp;
    }
    if (t == 0) pv[0][0] = 128 + g;
    __syncthreads();

    int cnt = 1, msb = 128, sel = 0;
    for (int lvl = 0; lvl < 4; lvl++) {      // levels 9..12
        const int nch = cnt * 2;
        for (int cb = 0; cb < nch; cb += 4) {
            const int c = cb + l;
            if (c < nch) {
                const int par = c >> 1;
                const int b   = c & 1;
                const int pc  = pv[sel][par] + (b + 1) * msb;
                const float* Qp = b ? Q1s : Q0s;
                const float* vp = cur + par * 128;
                float a0 = 0.f, a1 = 0.f, a2 = 0.f, a3 = 0.f;
                for (int i = 0; i < 128; i += 4) {
                    const float4 vv = *(const float4*)(vp + i);
                    a0 += vv.x * Qp[(i + 0) * 128 + j];
                    a1 += vv.y * Qp[(i + 1) * 128 + j];
                    a2 += vv.z * Qp[(i + 2) * 128 + j];
                    a3 += vv.w * Qp[(i + 3) * 128 + j];
                }
                const float acc = (a0 + a1) + (a2 + a3);
                nxt[c * 128 + j] = acc;
                g_table[pc * 128 + j] = acc;
                if (j == 0) pv[sel ^ 1][c] = pc;
            }
        }
        __syncthreads();
        float* tmp = cur; cur = nxt; nxt = tmp;
        sel ^= 1; cnt = nch; msb <<= 1;
    }
}

// ---------------------------------------------------------------------------
// Kernel 4: final embedding assembly (half the tokens per launch; two
// launches -- also shifts the ncu capture slot for attribution).
// ---------------------------------------------------------------------------
__global__ __launch_bounds__(256) void out_kernel(const int* __restrict__ tt,
                                                  const int* __restrict__ tv,
                                                  const int* __restrict__ np,
                                                  const float* __restrict__ ew,
                                                  float* __restrict__ out,
                                                  int base) {
    const int warp = threadIdx.x >> 5;
    const int lane = threadIdx.x & 31;
    const int tok  = base + blockIdx.x * 8 + warp;

    const int ty  = tt[tok];
    const int val = tv[tok];
    const int pos = np[tok];

    const float4 pv4 = *(const float4*)(g_table + pos * 128 + lane * 4);

    float4 cv;
    if (ty == 4) {
        int idx = val < 0 ? 0 : (val > 4095 ? 4095 : val);
        cv = *(const float4*)(g_table + idx * 128 + lane * 4);
    } else if (ty == 1) {
        cv = *(const float4*)(ew + (val + 1) * 128 + lane * 4);
    } else if (ty == 2) {
        cv = *(const float4*)(ew + (val + 5) * 128 + lane * 4);
    } else if (ty == 0) {
        cv = *(const float4*)(ew + lane * 4);
    } else if (ty == 3 && val == -1) {
        cv = *(const float4*)(ew + 10 * 128 + lane * 4);
    } else {
        cv = make_float4(0.f, 0.f, 0.f, 0.f);
    }

    float* o = out + (size_t)tok * 256;
    __stcs((float4*)(o + lane * 4), cv);
    __stcs((float4*)(o + 128 + lane * 4), pv4);
}

// ---------------------------------------------------------------------------
extern "C" void kernel_launch(void* const* d_in, const int* in_sizes, int n_in,
                              void* d_out, int out_size) {
    const int*   tt    = (const int*)d_in[0];   // token_types   [32,4096]
    const int*   tv    = (const int*)d_in[1];   // token_values  [32,4096]
    const int*   np    = (const int*)d_in[2];   // node_positions[32,4096]
    const float* prim  = (const float*)d_in[3]; // primitives    [2,128,128]
    const float* ident = (const float*)d_in[4]; // identity      [1,128]
    const float* ew    = (const float*)d_in[5]; // embed_weight  [11,128]
    float* out = (float*)d_out;

    const int lu_smem    = 128 * LU_PITCH * (int)sizeof(float);
    const int solve_smem = (128 * LU_PITCH + 128) * (int)sizeof(float);
    const int tbl_smem   = TBL_SMEM_FLOATS * (int)sizeof(float);

    cudaFuncSetAttribute(lu_kernel,    cudaFuncAttributeMaxDynamicSharedMemorySize, lu_smem);
    cudaFuncSetAttribute(solve_kernel, cudaFuncAttributeMaxDynamicSharedMemorySize, solve_smem);
    cudaFuncSetAttribute(table_kernel, cudaFuncAttributeMaxDynamicSharedMemorySize, tbl_smem);

    lu_kernel<<<2, 512, lu_smem>>>(prim);
    solve_kernel<<<32, 256, solve_smem>>>(prim);
    table_kernel<<<128, 512, tbl_smem>>>(ident);
    out_kernel<<<8192, 256>>>(tt, tv, np, ew, out, 0);
    out_kernel<<<8192, 256>>>(tt, tv, np, ew, out, 65536);
}

// round 11
// speedup vs baseline: 2.4592x; 1.0027x over previous
#include <cuda_runtime.h>
#include <cuda_bf16.h>

// Scratch (no allocations allowed -> __device__ globals)
__device__ float g_LU[2][128 * 128];     // LU factors of (I - A/2), row-major
__device__ float g_QT[2][128 * 128];     // QT[m][j*128+i] = Q[j][i]
__device__ float g_table[4096 * 128];    // pathemb table for every position value

// Inter-block phase flags (128B apart to avoid L2-line contention).
// Zero-initialized at load; RESET by the last table block each call -> replay-safe.
__device__ unsigned g_flags[3 * 32];     // [0]=c1 (lu done), [32]=c2 (solve done), [64]=c3

#define LU_PITCH 129
#define NBLOCKS  128
#define TBL_SMEM_FLOATS (2 * 16384 + 2 * 2048)   // 36864 floats = 144 KB

// ---------------------------------------------------------------------------
// Mega-kernel: LU (blocks 0-1) -> solve (blocks 0-15) -> table (blocks 0-127),
// chained via monotone atomic ready-flags. All 128 blocks are resident
// simultaneously (144KB dynamic smem -> 1 block/SM, 128 <= 148 SMs), so
// spin-waiting is deadlock-free.
// ---------------------------------------------------------------------------
__global__ __launch_bounds__(512, 1) void mega_kernel(const float* __restrict__ X,
                                                      const float* __restrict__ identity) {
    extern __shared__ float sm[];
    __shared__ float colbuf[2][128];
    __shared__ float rowbuf[2][128];
    __shared__ float pinvbuf[2];
    __shared__ int   pv[2][16];

    const int blk  = blockIdx.x;
    const int t    = threadIdx.x;
    const int tr   = t & 31;          // lane
    const int w    = t >> 5;          // warp id (0..15)

    // =========================== Phase 1: LU ===============================
    if (blk < 2) {
        const int m = blk;
        const float* Xm = X + m * 128 * 128;
        float* Xs = sm;                                  // 128*129

        for (int idx = t; idx < 128 * 128; idx += 512)
            Xs[(idx >> 7) * LU_PITCH + (idx & 127)] = Xm[idx];
        __syncthreads();

        // init M = I - 0.5*(tril(X) - tril(X)^T); warp w owns cols 8w..8w+7
        float reg[4][8];
#pragma unroll
        for (int s = 0; s < 4; s++) {
            const int r = tr + 32 * s;
#pragma unroll
            for (int q = 0; q < 8; q++) {
                const int c = 8 * w + q;
                float a = (r > c) ? Xs[r * LU_PITCH + c]
                        : ((r < c) ? -Xs[c * LU_PITCH + r] : 0.0f);
                reg[s][q] = ((r == c) ? 1.0f : 0.0f) - 0.5f * a;
            }
        }
        if (w == 0) {
#pragma unroll
            for (int s = 0; s < 4; s++) colbuf[0][tr + 32 * s] = reg[s][0];
        }
        if (tr == 0) {
#pragma unroll
            for (int q = 0; q < 8; q++) rowbuf[0][8 * w + q] = reg[0][q];
            if (w == 0) pinvbuf[0] = 1.0f / reg[0][0];
        }

        for (int k = 0; k < 128; k++) {
            __syncthreads();
            const int p = k & 1;
            if (8 * w + 7 >= k) {                        // warp-uniform dead skip
                const float pinv = pinvbuf[p];
                float l[4];
#pragma unroll
                for (int s = 0; s < 4; s++) l[s] = colbuf[p][tr + 32 * s] * pinv;
                float rb[8];
#pragma unroll
                for (int q = 0; q < 8; q++) rb[q] = rowbuf[p][8 * w + q];
#pragma unroll
                for (int s = 0; s < 4; s++) {
                    const int r = tr + 32 * s;
                    const bool act = (r > k);
#pragma unroll
                    for (int q = 0; q < 8; q++) {
                        const int c = 8 * w + q;
                        if (act) {
                            if (c > k)       reg[s][q] -= l[s] * rb[q];
                            else if (c == k) reg[s][q]  = l[s];
                        }
                    }
                }
                if (k < 127) {
                    const int kn = k + 1;
                    if (w == (kn >> 3)) {                // column kn owner warp
                        const int qn = kn & 7;
#pragma unroll
                        for (int s = 0; s < 4; s++) {
                            float v = reg[s][0];
#pragma unroll
                            for (int qq = 1; qq < 8; qq++)
                                if (qq == qn) v = reg[s][qq];
                            colbuf[p ^ 1][tr + 32 * s] = v;
                        }
                    }
                    if (tr == (kn & 31)) {               // row kn lane
                        const int sn = kn >> 5;
                        float vr[8];
#pragma unroll
                        for (int q = 0; q < 8; q++) {
                            float v = reg[0][q];
#pragma unroll
                            for (int ss = 1; ss < 4; ss++)
                                if (ss == sn) v = reg[ss][q];
                            vr[q] = v;
                            rowbuf[p ^ 1][8 * w + q] = v;
                        }
                        if (w == (kn >> 3)) {
                            const int qn = kn & 7;
                            float v = vr[0];
#pragma unroll
                            for (int qq = 1; qq < 8; qq++)
                                if (qq == qn) v = vr[qq];
                            pinvbuf[p ^ 1] = 1.0f / v;
                        }
                    }
                }
            }
        }
        __syncthreads();
#pragma unroll
        for (int s = 0; s < 4; s++) {
            const int r = tr + 32 * s;
#pragma unroll
            for (int q = 0; q < 8; q++)
                Xs[r * LU_PITCH + 8 * w + q] = reg[s][q];
        }
        __syncthreads();
        for (int idx = t; idx < 128 * 128; idx += 512)
            g_LU[m][idx] = Xs[(idx >> 7) * LU_PITCH + (idx & 127)];
        __syncthreads();
        __threadfence();
        if (t == 0) atomicAdd(&g_flags[0], 1u);          // c1++
    }

    // =========================== Phase 2: solve =============================
    if (blk < 16) {
        if (t == 0) while (atomicAdd(&g_flags[0], 0u) < 2u) {}
        __syncthreads();
        __threadfence();

        const int m = blk >> 3;
        const int j = ((blk & 7) << 4) + w;              // 16 RHS per block
        const float* Xm  = X + m * 128 * 128;
        const float* LUg = g_LU[m];
        float* LUs   = sm;                               // 128*129
        float* rdiag = sm + 128 * LU_PITCH;              // 128

        for (int idx = t; idx < 128 * 128; idx += 512)
            LUs[(idx >> 7) * LU_PITCH + (idx & 127)] = LUg[idx];
        if (t < 128) rdiag[t] = 1.0f / LUg[t * 128 + t];
        __syncthreads();

        const int lane = tr;
        float y0, y1, y2, y3;
        {
            const int i0 = lane, i1 = lane + 32, i2 = lane + 64, i3 = lane + 96;
            float a0 = (i0 > j) ? Xm[i0 * 128 + j] : ((i0 < j) ? -Xm[j * 128 + i0] : 0.0f);
            float a1 = (i1 > j) ? Xm[i1 * 128 + j] : ((i1 < j) ? -Xm[j * 128 + i1] : 0.0f);
            float a2 = (i2 > j) ? Xm[i2 * 128 + j] : ((i2 < j) ? -Xm[j * 128 + i2] : 0.0f);
            float a3 = (i3 > j) ? Xm[i3 * 128 + j] : ((i3 < j) ? -Xm[j * 128 + i3] : 0.0f);
            y0 = ((i0 == j) ? 1.0f : 0.0f) + 0.5f * a0;
            y1 = ((i1 == j) ? 1.0f : 0.0f) + 0.5f * a1;
            y2 = ((i2 == j) ? 1.0f : 0.0f) + 0.5f * a2;
            y3 = ((i3 == j) ? 1.0f : 0.0f) + 0.5f * a3;
        }
        const unsigned FULL = 0xffffffffu;

        // forward: L z = r (unit lower)
#pragma unroll 4
        for (int kk = 0; kk < 32; kk++) {
            const float yk = __shfl_sync(FULL, y0, kk);
            const float* col = LUs + kk;
            if (lane > kk) y0 -= col[lane * LU_PITCH] * yk;
            y1 -= col[(lane + 32) * LU_PITCH] * yk;
            y2 -= col[(lane + 64) * LU_PITCH] * yk;
            y3 -= col[(lane + 96) * LU_PITCH] * yk;
        }
#pragma unroll 4
        for (int kk = 0; kk < 32; kk++) {
            const float yk = __shfl_sync(FULL, y1, kk);
            const float* col = LUs + 32 + kk;
            if (lane > kk) y1 -= col[(lane + 32) * LU_PITCH] * yk;
            y2 -= col[(lane + 64) * LU_PITCH] * yk;
            y3 -= col[(lane + 96) * LU_PITCH] * yk;
        }
#pragma unroll 4
        for (int kk = 0; kk < 32; kk++) {
            const float yk = __shfl_sync(FULL, y2, kk);
            const float* col = LUs + 64 + kk;
            if (lane > kk) y2 -= col[(lane + 64) * LU_PITCH] * yk;
            y3 -= col[(lane + 96) * LU_PITCH] * yk;
        }
#pragma unroll 4
        for (int kk = 0; kk < 31; kk++) {
            const float yk = __shfl_sync(FULL, y3, kk);
            if (lane > kk) y3 -= LUs[(lane + 96) * LU_PITCH + 96 + kk] * yk;
        }
        // backward: U q = z
#pragma unroll 4
        for (int kk = 31; kk >= 0; kk--) {
            const int k = 96 + kk;
            const float yk = __shfl_sync(FULL, y3, kk) * rdiag[k];
            if (lane == kk) y3 = yk;
            else if (lane < kk) y3 -= LUs[(lane + 96) * LU_PITCH + k] * yk;
            y0 -= LUs[lane * LU_PITCH + k] * yk;
            y1 -= LUs[(lane + 32) * LU_PITCH + k] * yk;
            y2 -= LUs[(lane + 64) * LU_PITCH + k] * yk;
        }
#pragma unroll 4
        for (int kk = 31; kk >= 0; kk--) {
            const int k = 64 + kk;
            const float yk = __shfl_sync(FULL, y2, kk) * rdiag[k];
            if (lane == kk) y2 = yk;
            else if (lane < kk) y2 -= LUs[(lane + 64) * LU_PITCH + k] * yk;
            y0 -= LUs[lane * LU_PITCH + k] * yk;
            y1 -= LUs[(lane + 32) * LU_PITCH + k] * yk;
        }
#pragma unroll 4
        for (int kk = 31; kk >= 0; kk--) {
            const int k = 32 + kk;
            const float yk = __shfl_sync(FULL, y1, kk) * rdiag[k];
            if (lane == kk) y1 = yk;
            else if (lane < kk) y1 -= LUs[(lane + 32) * LU_PITCH + k] * yk;
            y0 -= LUs[lane * LU_PITCH + k] * yk;
        }
#pragma unroll 4
        for (int kk = 31; kk >= 0; kk--) {
            const float yk = __shfl_sync(FULL, y0, kk) * rdiag[kk];
            if (lane == kk) y0 = yk;
            else if (lane < kk) y0 -= LUs[lane * LU_PITCH + kk] * yk;
        }
        float* dst = g_QT[m] + j * 128 + lane;
        dst[0] = y0; dst[32] = y1; dst[64] = y2; dst[96] = y3;

        __syncthreads();
        __threadfence();
        if (t == 0) atomicAdd(&g_flags[32], 1u);         // c2++
    }

    // =========================== Phase 3: table =============================
    if (t == 0) while (atomicAdd(&g_flags[32], 0u) < 16u) {}
    __syncthreads();
    __threadfence();

    {
        float* Q0s  = sm;
        float* Q1s  = sm + 16384;
        float* bufA = sm + 32768;
        float* bufB = sm + 34816;
        const int g = blk;
        const int l = t >> 7;
        const int j = t & 127;

        {
            const float4* src = (const float4*)g_QT;
            float4* dst = (float4*)sm;
            for (int i = t; i < 8192; i += 512) dst[i] = src[i];
        }
        if (t < 128) bufA[j] = identity[j];
        if (g == 0 && t < 128) {
            g_table[0 + j]   = identity[j];
            g_table[128 + j] = identity[j];
        }
        __syncthreads();

        float* cur = bufA;
        float* nxt = bufB;
        for (int d = 0; d < 7; d++) {                    // root path: levels 2..8
            if (t < 128) {
                const int b = (g >> d) & 1;
                const float* Qp = b ? Q1s : Q0s;
                float a0 = 0.f, a1 = 0.f, a2 = 0.f, a3 = 0.f;
                for (int i = 0; i < 128; i += 4) {
                    const float4 vv = *(const float4*)(cur + i);
                    a0 += vv.x * Qp[(i + 0) * 128 + j];
                    a1 += vv.y * Qp[(i + 1) * 128 + j];
                    a2 += vv.z * Qp[(i + 2) * 128 + j];
                    a3 += vv.w * Qp[(i + 3) * 128 + j];
                }
                const float acc = (a0 + a1) + (a2 + a3);
                nxt[j] = acc;
                const int p = (g & ((2 << d) - 1)) | (2 << d);
                g_table[p * 128 + j] = acc;
            }
            __syncthreads();
            float* tmp = cur; cur = nxt; nxt = tmp;
        }
        if (t == 0) pv[0][0] = 128 + g;
        __syncthreads();

        int cnt = 1, msb = 128, sel = 0;
        for (int lvl = 0; lvl < 4; lvl++) {              // levels 9..12
            const int nch = cnt * 2;
            for (int cb = 0; cb < nch; cb += 4) {
                const int c = cb + l;
                if (c < nch) {
                    const int par = c >> 1;
                    const int b   = c & 1;
                    const int pc  = pv[sel][par] + (b + 1) * msb;
                    const float* Qp = b ? Q1s : Q0s;
                    const float* vp = cur + par * 128;
                    float a0 = 0.f, a1 = 0.f, a2 = 0.f, a3 = 0.f;
                    for (int i = 0; i < 128; i += 4) {
                        const float4 vv = *(const float4*)(vp + i);
                        a0 += vv.x * Qp[(i + 0) * 128 + j];
                        a1 += vv.y * Qp[(i + 1) * 128 + j];
                        a2 += vv.z * Qp[(i + 2) * 128 + j];
                        a3 += vv.w * Qp[(i + 3) * 128 + j];
                    }
                    const float acc = (a0 + a1) + (a2 + a3);
                    nxt[c * 128 + j] = acc;
                    g_table[pc * 128 + j] = acc;
                    if (j == 0) pv[sel ^ 1][c] = pc;
                }
            }
            __syncthreads();
            float* tmp = cur; cur = nxt; nxt = tmp;
            sel ^= 1; cnt = nch; msb <<= 1;
        }
    }

    // ======== flag reset (replay-safe): last table block zeroes all ========
    __syncthreads();
    if (t == 0) {
        if (atomicAdd(&g_flags[64], 1u) == NBLOCKS - 1) {
            atomicExch(&g_flags[0], 0u);
            atomicExch(&g_flags[32], 0u);
            atomicExch(&g_flags[64], 0u);
            __threadfence();
        }
    }
}

// ---------------------------------------------------------------------------
// Kernel 2: final embedding assembly. One warp per token, float4 streaming
// stores. 128 MB write -> HBM-bound.
// ---------------------------------------------------------------------------
__global__ __launch_bounds__(256) void out_kernel(const int* __restrict__ tt,
                                                  const int* __restrict__ tv,
                                                  const int* __restrict__ np,
                                                  const float* __restrict__ ew,
                                                  float* __restrict__ out) {
    const int warp = threadIdx.x >> 5;
    const int lane = threadIdx.x & 31;
    const int tok  = blockIdx.x * 8 + warp;      // < 131072

    const int ty  = tt[tok];
    const int val = tv[tok];
    const int pos = np[tok];

    const float4 pv4 = *(const float4*)(g_table + pos * 128 + lane * 4);

    float4 cv;
    if (ty == 4) {
        int idx = val < 0 ? 0 : (val > 4095 ? 4095 : val);
        cv = *(const float4*)(g_table + idx * 128 + lane * 4);
    } else if (ty == 1) {
        cv = *(const float4*)(ew + (val + 1) * 128 + lane * 4);
    } else if (ty == 2) {
        cv = *(const float4*)(ew + (val + 5) * 128 + lane * 4);
    } else if (ty == 0) {
        cv = *(const float4*)(ew + lane * 4);
    } else if (ty == 3 && val == -1) {
        cv = *(const float4*)(ew + 10 * 128 + lane * 4);
    } else {
        cv = make_float4(0.f, 0.f, 0.f, 0.f);
    }

    float* o = out + (size_t)tok * 256;
    __stcs((float4*)(o + lane * 4), cv);
    __stcs((float4*)(o + 128 + lane * 4), pv4);
}

// ---------------------------------------------------------------------------
extern "C" void kernel_launch(void* const* d_in, const int* in_sizes, int n_in,
                              void* d_out, int out_size) {
    const int*   tt    = (const int*)d_in[0];   // token_types   [32,4096]
    const int*   tv    = (const int*)d_in[1];   // token_values  [32,4096]
    const int*   np    = (const int*)d_in[2];   // node_positions[32,4096]
    const float* prim  = (const float*)d_in[3]; // primitives    [2,128,128]
    const float* ident = (const float*)d_in[4]; // identity      [1,128]
    const float* ew    = (const float*)d_in[5]; // embed_weight  [11,128]
    float* out = (float*)d_out;

    const int mega_smem = TBL_SMEM_FLOATS * (int)sizeof(float);   // 147456 B
    cudaFuncSetAttribute(mega_kernel, cudaFuncAttributeMaxDynamicSharedMemorySize, mega_smem);

    mega_kernel<<<NBLOCKS, 512, mega_smem>>>(prim, ident);
    out_kernel<<<16384, 256>>>(tt, tv, np, ew, out);
}